// round 2
// baseline (speedup 1.0000x reference)
#include <cuda_runtime.h>

namespace {

constexpr int T_ = 64;
constexpr int IN_ = 16;
constexpr int H_ = 128;
constexpr int DEPTH_ = 3;
constexpr int PITCH = 132;   // floats; 132 % 32 == 4, float4 view stride 33 -> conflict-free LDS.128
constexpr int PITCH4 = 33;
constexpr float EPS = 1e-5f;

struct __align__(16) Smem {
    float hs[T_ * H_];        // token state, pitch 128 (float4-friendly broadcasts)
    float qb[T_ * PITCH];     // Q, then ctx, then scratch
    float kb[T_ * PITCH];
    float vb[T_ * PITCH];
    float wb[H_ * H_];        // staged weight matrix
    float feat[T_ * IN_];
    float valid[T_];
    float red[2][8];          // per-group reduction scratch
};

__device__ __forceinline__ void gbar(int g) {
    asm volatile("bar.sync %0, 128;" :: "r"(g + 1) : "memory");
}

// sum-reduce (a,b) over the 128 threads of group g
__device__ __forceinline__ void reduce2(float& a, float& b, int g, int wig, int lane, float* red) {
#pragma unroll
    for (int o = 16; o > 0; o >>= 1) {
        a += __shfl_down_sync(0xffffffffu, a, o);
        b += __shfl_down_sync(0xffffffffu, b, o);
    }
    if (lane == 0) { red[wig * 2] = a; red[wig * 2 + 1] = b; }
    gbar(g);
    a = red[0] + red[2] + red[4] + red[6];
    b = red[1] + red[3] + red[5] + red[7];
    gbar(g);  // protect red from next iteration's writes
}

__device__ __forceinline__ void load_w(float* dst, const float* src, int n4, int tid) {
    const float4* s4 = reinterpret_cast<const float4*>(src);
    float4* d4 = reinterpret_cast<float4*>(dst);
    for (int i = tid; i < n4; i += 256) d4[i] = s4[i];
}

// out[t][h] = bias + sum_i hs[t][i] * W[i][h], for this group's 32 tokens.
__device__ __forceinline__ void gemm_group(const float* __restrict__ hsbuf,
                                           const float* __restrict__ wb,
                                           float bias, int g, int h,
                                           float* __restrict__ outp, int opitch) {
    const float4* x4 = reinterpret_cast<const float4*>(hsbuf);
    for (int tile = 0; tile < 4; ++tile) {
        int t0 = g * 32 + tile * 8;
        float acc[8];
#pragma unroll
        for (int tc = 0; tc < 8; ++tc) acc[tc] = bias;
#pragma unroll 4
        for (int i = 0; i < H_; i += 4) {
            float w0 = wb[(i + 0) * H_ + h];
            float w1 = wb[(i + 1) * H_ + h];
            float w2 = wb[(i + 2) * H_ + h];
            float w3 = wb[(i + 3) * H_ + h];
#pragma unroll
            for (int tc = 0; tc < 8; ++tc) {
                float4 x = x4[(t0 + tc) * (H_ / 4) + (i >> 2)];
                acc[tc] = fmaf(x.x, w0, acc[tc]);
                acc[tc] = fmaf(x.y, w1, acc[tc]);
                acc[tc] = fmaf(x.z, w2, acc[tc]);
                acc[tc] = fmaf(x.w, w3, acc[tc]);
            }
        }
#pragma unroll
        for (int tc = 0; tc < 8; ++tc) outp[(t0 + tc) * opitch + h] = acc[tc];
    }
}

__global__ void __launch_bounds__(256, 1) fused_lane_encoder(
    const float* __restrict__ feat, const float* __restrict__ masks,
    const float* __restrict__ W_emb, const float* __restrict__ b_emb,
    const float* __restrict__ g_emb, const float* __restrict__ beta_emb,
    const float* __restrict__ W_enc, const float* __restrict__ b_enc,
    const float* __restrict__ g_enc, const float* __restrict__ beta_enc,
    const float* __restrict__ Wq, const float* __restrict__ bq,
    const float* __restrict__ Wk, const float* __restrict__ bk,
    const float* __restrict__ Wv, const float* __restrict__ bv,
    const float* __restrict__ ln_g, const float* __restrict__ ln_b,
    float* __restrict__ out)
{
    extern __shared__ float smem_raw[];
    Smem* sm = reinterpret_cast<Smem*>(smem_raw);

    const int tid  = threadIdx.x;
    const int h    = tid & 127;
    const int g    = tid >> 7;       // token group 0/1
    const int lane = tid & 31;
    const int wid  = tid >> 5;       // 0..7
    const int wig  = wid & 3;        // warp-in-group
    const int blk  = blockIdx.x;
    float* red = sm->red[g];

    // ---- stage inputs ----
    {
        const float4* s4 = reinterpret_cast<const float4*>(feat + (size_t)blk * T_ * IN_);
        float4* d4 = reinterpret_cast<float4*>(sm->feat);
        for (int i = tid; i < T_ * IN_ / 4; i += 256) d4[i] = s4[i];
    }
    if (tid < T_) sm->valid[tid] = 1.0f - masks[(size_t)blk * T_ + tid];
    load_w(sm->wb, W_emb, IN_ * H_ / 4, tid);
    __syncthreads();

    // ---- Phase 1: emb = relu(LN(feat @ W_emb + b)) ----
    {
        float bb = b_emb[h], gg = g_emb[h], be = beta_emb[h];
        for (int tt = 0; tt < 32; ++tt) {
            int t = g * 32 + tt;
            float acc = bb;
#pragma unroll
            for (int i = 0; i < IN_; ++i)
                acc = fmaf(sm->feat[t * IN_ + i], sm->wb[i * H_ + h], acc);
            float s = acc, ss = acc * acc;
            reduce2(s, ss, g, wig, lane, red);
            float mean = s * (1.f / H_);
            float var  = ss * (1.f / H_) - mean * mean;
            float v = gg * (acc - mean) * rsqrtf(var + EPS) + be;
            sm->hs[t * H_ + h] = fmaxf(v, 0.f);
        }
    }
    __syncthreads();

    // ---- Phase 2: enc = relu(LN(hs @ W_enc + b)), in place ----
    load_w(sm->wb, W_enc, H_ * H_ / 4, tid);
    __syncthreads();
    {
        float bb = b_enc[h], gg = g_enc[h], be = beta_enc[h];
        const float4* x4 = reinterpret_cast<const float4*>(sm->hs);
        for (int tile = 0; tile < 4; ++tile) {
            int t0 = g * 32 + tile * 8;
            float acc[8];
#pragma unroll
            for (int tc = 0; tc < 8; ++tc) acc[tc] = bb;
#pragma unroll 4
            for (int i = 0; i < H_; i += 4) {
                float w0 = sm->wb[(i + 0) * H_ + h];
                float w1 = sm->wb[(i + 1) * H_ + h];
                float w2 = sm->wb[(i + 2) * H_ + h];
                float w3 = sm->wb[(i + 3) * H_ + h];
#pragma unroll
                for (int tc = 0; tc < 8; ++tc) {
                    float4 x = x4[(t0 + tc) * (H_ / 4) + (i >> 2)];
                    acc[tc] = fmaf(x.x, w0, acc[tc]);
                    acc[tc] = fmaf(x.y, w1, acc[tc]);
                    acc[tc] = fmaf(x.z, w2, acc[tc]);
                    acc[tc] = fmaf(x.w, w3, acc[tc]);
                }
            }
            // first reduce2's barrier guarantees all group reads of rows t0..t0+7 done
#pragma unroll
            for (int tc = 0; tc < 8; ++tc) {
                float s = acc[tc], ss = acc[tc] * acc[tc];
                reduce2(s, ss, g, wig, lane, red);
                float mean = s * (1.f / H_);
                float var  = ss * (1.f / H_) - mean * mean;
                float v = gg * (acc[tc] - mean) * rsqrtf(var + EPS) + be;
                sm->hs[(t0 + tc) * H_ + h] = fmaxf(v, 0.f);
            }
        }
    }
    __syncthreads();

    // ---- Phase 3: DEPTH transformer layers ----
    for (int d = 0; d < DEPTH_; ++d) {
        // Q = hs @ Wq + bq
        load_w(sm->wb, Wq + (size_t)d * H_ * H_, H_ * H_ / 4, tid);
        __syncthreads();
        gemm_group(sm->hs, sm->wb, bq[d * H_ + h], g, h, sm->qb, PITCH);
        __syncthreads();
        // K
        load_w(sm->wb, Wk + (size_t)d * H_ * H_, H_ * H_ / 4, tid);
        __syncthreads();
        gemm_group(sm->hs, sm->wb, bk[d * H_ + h], g, h, sm->kb, PITCH);
        __syncthreads();
        // V
        load_w(sm->wb, Wv + (size_t)d * H_ * H_, H_ * H_ / 4, tid);
        __syncthreads();
        gemm_group(sm->hs, sm->wb, bv[d * H_ + h], g, h, sm->vb, PITCH);
        __syncthreads();

        // attention: warp w owns queries [w*8, w*8+8), 4 at a time
        {
            const float4* Q4 = reinterpret_cast<const float4*>(sm->qb);
            const float4* K4 = reinterpret_cast<const float4*>(sm->kb);
            const float4* V4 = reinterpret_cast<const float4*>(sm->vb);
            float4* C4 = reinterpret_cast<float4*>(sm->qb);   // ctx overwrites consumed Q rows
            const float vk1 = sm->valid[lane];
            const float vk2 = sm->valid[lane + 32];
            const int hsel = lane >> 4;                        // ctx dims 4*lane..: head = lane/16

            for (int qp = 0; qp < 2; ++qp) {
                const int tq0 = wid * 8 + qp * 4;
                float p_lo[2][4], p_hi[2][4];
#pragma unroll
                for (int head = 0; head < 2; ++head) {
                    const int base = head * 16;
                    float a1[4] = {0.f, 0.f, 0.f, 0.f};
                    float a2[4] = {0.f, 0.f, 0.f, 0.f};
#pragma unroll 4
                    for (int c = 0; c < 16; ++c) {
                        float4 k1 = K4[lane * PITCH4 + base + c];
                        float4 k2 = K4[(lane + 32) * PITCH4 + base + c];
#pragma unroll
                        for (int qq = 0; qq < 4; ++qq) {
                            float4 qv = Q4[(tq0 + qq) * PITCH4 + base + c];
                            a1[qq] = fmaf(qv.x, k1.x, fmaf(qv.y, k1.y, fmaf(qv.z, k1.z, fmaf(qv.w, k1.w, a1[qq]))));
                            a2[qq] = fmaf(qv.x, k2.x, fmaf(qv.y, k2.y, fmaf(qv.z, k2.z, fmaf(qv.w, k2.w, a2[qq]))));
                        }
                    }
#pragma unroll
                    for (int qq = 0; qq < 4; ++qq) {
                        float vq = sm->valid[tq0 + qq];
                        float s1 = a1[qq] * 0.125f + (1.f - vq * vk1) * -10000.f;
                        float s2 = a2[qq] * 0.125f + (1.f - vq * vk2) * -10000.f;
                        float mx = fmaxf(s1, s2);
#pragma unroll
                        for (int o = 16; o > 0; o >>= 1) mx = fmaxf(mx, __shfl_xor_sync(0xffffffffu, mx, o));
                        float e1 = __expf(s1 - mx), e2 = __expf(s2 - mx);
                        float sum = e1 + e2;
#pragma unroll
                        for (int o = 16; o > 0; o >>= 1) sum += __shfl_xor_sync(0xffffffffu, sum, o);
                        float inv = 1.f / sum;
                        p_lo[head][qq] = e1 * inv;
                        p_hi[head][qq] = e2 * inv;
                    }
                }
                // ctx: lane owns output dims [4*lane, 4*lane+4)
                float4 ctx[4];
#pragma unroll
                for (int qq = 0; qq < 4; ++qq) ctx[qq] = make_float4(0.f, 0.f, 0.f, 0.f);
                for (int j = 0; j < T_; ++j) {
                    float4 v4 = V4[j * PITCH4 + lane];
                    int src = j & 31;
                    bool lo = j < 32;
#pragma unroll
                    for (int qq = 0; qq < 4; ++qq) {
                        float q0 = lo ? p_lo[0][qq] : p_hi[0][qq];
                        float q1 = lo ? p_lo[1][qq] : p_hi[1][qq];
                        float pj0 = __shfl_sync(0xffffffffu, q0, src);
                        float pj1 = __shfl_sync(0xffffffffu, q1, src);
                        float pj = hsel ? pj1 : pj0;
                        ctx[qq].x = fmaf(pj, v4.x, ctx[qq].x);
                        ctx[qq].y = fmaf(pj, v4.y, ctx[qq].y);
                        ctx[qq].z = fmaf(pj, v4.z, ctx[qq].z);
                        ctx[qq].w = fmaf(pj, v4.w, ctx[qq].w);
                    }
                }
#pragma unroll
                for (int qq = 0; qq < 4; ++qq) C4[(tq0 + qq) * PITCH4 + lane] = ctx[qq];
            }
        }
        __syncthreads();

        // hs = LN(relu(ctx) + hs)
        {
            float gg = ln_g[d * H_ + h], bb = ln_b[d * H_ + h];
            for (int tt = 0; tt < 32; ++tt) {
                int t = g * 32 + tt;
                float x = fmaxf(sm->qb[t * PITCH + h], 0.f) + sm->hs[t * H_ + h];
                float s = x, ss = x * x;
                reduce2(s, ss, g, wig, lane, red);
                float mean = s * (1.f / H_);
                float var  = ss * (1.f / H_) - mean * mean;
                sm->hs[t * H_ + h] = gg * (x - mean) * rsqrtf(var + EPS) + bb;
            }
        }
        __syncthreads();
    }

    // ---- Phase 4: max over T ----
    float m = -3.4e38f;
    for (int tt = 0; tt < 32; ++tt)
        m = fmaxf(m, sm->hs[(g * 32 + tt) * H_ + h]);
    __syncthreads();
    sm->qb[g * H_ + h] = m;
    __syncthreads();
    if (g == 0)
        out[(size_t)blk * H_ + h] = fmaxf(sm->qb[h], sm->qb[H_ + h]);
}

} // namespace

extern "C" void kernel_launch(void* const* d_in, const int* in_sizes, int n_in,
                              void* d_out, int out_size) {
    const float* feat     = (const float*)d_in[0];
    const float* masks    = (const float*)d_in[1];
    const float* W_emb    = (const float*)d_in[2];
    const float* b_emb    = (const float*)d_in[3];
    const float* g_emb    = (const float*)d_in[4];
    const float* beta_emb = (const float*)d_in[5];
    const float* W_enc    = (const float*)d_in[6];
    const float* b_enc    = (const float*)d_in[7];
    const float* g_enc    = (const float*)d_in[8];
    const float* beta_enc = (const float*)d_in[9];
    const float* Wq       = (const float*)d_in[10];
    const float* bq       = (const float*)d_in[11];
    const float* Wk       = (const float*)d_in[12];
    const float* bk       = (const float*)d_in[13];
    const float* Wv       = (const float*)d_in[14];
    const float* bv       = (const float*)d_in[15];
    const float* ln_g     = (const float*)d_in[16];
    const float* ln_b     = (const float*)d_in[17];
    float* out = (float*)d_out;

    int nseq = in_sizes[0] / (T_ * IN_);   // B*L = 4096
    size_t smem = sizeof(Smem);            // ~200 KB
    cudaFuncSetAttribute(fused_lane_encoder,
                         cudaFuncAttributeMaxDynamicSharedMemorySize, (int)smem);

    fused_lane_encoder<<<nseq, 256, smem>>>(
        feat, masks, W_emb, b_emb, g_emb, beta_emb,
        W_enc, b_enc, g_enc, beta_enc,
        Wq, bq, Wk, bk, Wv, bv, ln_g, ln_b, out);
}

// round 4
// speedup vs baseline: 1.4876x; 1.4876x over previous
#include <cuda_runtime.h>

namespace {

typedef unsigned long long u64;

constexpr int T_ = 64;
constexpr int IN_ = 16;
constexpr int H_ = 128;
constexpr int DEPTH_ = 3;
constexpr int PITCH4 = 33;          // float4 row pitch for Q/K/V buffers (132 floats)
constexpr float EPS = 1e-5f;
constexpr int NTHREADS = 512;

// ---------------- packed weights in global scratch ----------------
// g_wpk[row*128 + h] = (W[2*m][h], W[2*m+1][h])  (k-pair packing)
// rows: emb 8 | enc 64 | (Wq,Wk,Wv) x 3 layers, 64 each
constexpr int ROWS_EMB = 8;
constexpr int ROWS_MAT = 64;
constexpr int OFF_EMB = 0;
constexpr int OFF_ENC = ROWS_EMB * 128;
__host__ __device__ constexpr int off_qkv(int d, int w) {
    return (ROWS_EMB + ROWS_MAT + (d * 3 + w) * ROWS_MAT) * 128;
}
constexpr int WPK_TOTAL = (ROWS_EMB + ROWS_MAT + 9 * ROWS_MAT) * 128;

__device__ float2 g_wpk[WPK_TOTAL];

__global__ void pack_weights(const float* __restrict__ W_emb,
                             const float* __restrict__ W_enc,
                             const float* __restrict__ Wq,
                             const float* __restrict__ Wk,
                             const float* __restrict__ Wv) {
    int i = blockIdx.x * 256 + threadIdx.x;
    if (i >= WPK_TOTAL) return;
    int h = i & 127;
    int row = i >> 7;
    const float* src;
    int m;
    if (row < ROWS_EMB) { src = W_emb; m = row; }
    else if (row < ROWS_EMB + ROWS_MAT) { src = W_enc; m = row - ROWS_EMB; }
    else {
        int r = row - (ROWS_EMB + ROWS_MAT);
        int mat = r >> 6; m = r & 63;
        int d = mat / 3, w = mat % 3;
        src = (w == 0 ? Wq : (w == 1 ? Wk : Wv)) + d * H_ * H_;
    }
    g_wpk[i] = make_float2(src[(2 * m) * H_ + h], src[(2 * m + 1) * H_ + h]);
}

// ---------------- f32x2 helpers ----------------
union F4 { float4 v; u64 u[2]; };

__device__ __forceinline__ void ffma2(u64& d, u64 a, u64 b) {
    asm("fma.rn.f32x2 %0, %1, %2, %0;" : "+l"(d) : "l"(a), "l"(b));
}
__device__ __forceinline__ u64 pk2(float lo, float hi) {
    u64 r; asm("mov.b64 %0, {%1, %2};" : "=l"(r) : "f"(lo), "f"(hi)); return r;
}
__device__ __forceinline__ float hsum2(u64 v) {
    float lo, hi; asm("mov.b64 {%0, %1}, %2;" : "=f"(lo), "=f"(hi) : "l"(v));
    return lo + hi;
}

__device__ __forceinline__ float warp_sum(float v) {
#pragma unroll
    for (int o = 16; o > 0; o >>= 1) v += __shfl_xor_sync(0xffffffffu, v, o);
    return v;
}
__device__ __forceinline__ float warp_max(float v) {
#pragma unroll
    for (int o = 16; o > 0; o >>= 1) v = fmaxf(v, __shfl_xor_sync(0xffffffffu, v, o));
    return v;
}

// warp-local layernorm over H=128 (32 lanes x 4 values)
__device__ __forceinline__ float4 ln_warp(float4 x, float4 gm, float4 bt) {
    float s  = warp_sum(x.x + x.y + x.z + x.w);
    float ss = warp_sum(x.x * x.x + x.y * x.y + x.z * x.z + x.w * x.w);
    float mean = s * (1.f / H_);
    float var  = ss * (1.f / H_) - mean * mean;
    float inv  = rsqrtf(var + EPS);
    return make_float4(gm.x * (x.x - mean) * inv + bt.x,
                       gm.y * (x.y - mean) * inv + bt.y,
                       gm.z * (x.z - mean) * inv + bt.z,
                       gm.w * (x.w - mean) * inv + bt.w);
}

// res[t] (float4, h = 4l..4l+4) = bias + x[t] @ W, K=128, for 4 tokens t0..t0+3.
__device__ __forceinline__ void gemm128(const float4* __restrict__ wp4,
                                        const float4* __restrict__ x4,
                                        int t0, int l, float4 bias, float4 res[4]) {
    u64 acc[4][4] = {};
#pragma unroll 2
    for (int kb = 0; kb < 32; ++kb) {
        const float4* w0 = wp4 + (2 * kb) * 64 + 2 * l;
        const float4* w1 = wp4 + (2 * kb + 1) * 64 + 2 * l;
        F4 A0, A1, B0, B1;
        A0.v = w0[0]; A1.v = w0[1];
        B0.v = w1[0]; B1.v = w1[1];
#pragma unroll
        for (int t = 0; t < 4; ++t) {
            F4 x; x.v = x4[(t0 + t) * 32 + kb];
            ffma2(acc[t][0], x.u[0], A0.u[0]);
            ffma2(acc[t][0], x.u[1], B0.u[0]);
            ffma2(acc[t][1], x.u[0], A0.u[1]);
            ffma2(acc[t][1], x.u[1], B0.u[1]);
            ffma2(acc[t][2], x.u[0], A1.u[0]);
            ffma2(acc[t][2], x.u[1], B1.u[0]);
            ffma2(acc[t][3], x.u[0], A1.u[1]);
            ffma2(acc[t][3], x.u[1], B1.u[1]);
        }
    }
#pragma unroll
    for (int t = 0; t < 4; ++t)
        res[t] = make_float4(hsum2(acc[t][0]) + bias.x, hsum2(acc[t][1]) + bias.y,
                             hsum2(acc[t][2]) + bias.z, hsum2(acc[t][3]) + bias.w);
}

// K = 16 variant (emb), x read from global
__device__ __forceinline__ void gemm16(const float4* __restrict__ wp4,
                                       const float4* __restrict__ xg4,
                                       int t0, int l, float4 bias, float4 res[4]) {
    u64 acc[4][4] = {};
#pragma unroll
    for (int kb = 0; kb < 4; ++kb) {
        const float4* w0 = wp4 + (2 * kb) * 64 + 2 * l;
        const float4* w1 = wp4 + (2 * kb + 1) * 64 + 2 * l;
        F4 A0, A1, B0, B1;
        A0.v = w0[0]; A1.v = w0[1];
        B0.v = w1[0]; B1.v = w1[1];
#pragma unroll
        for (int t = 0; t < 4; ++t) {
            F4 x; x.v = xg4[(t0 + t) * 4 + kb];
            ffma2(acc[t][0], x.u[0], A0.u[0]);
            ffma2(acc[t][0], x.u[1], B0.u[0]);
            ffma2(acc[t][1], x.u[0], A0.u[1]);
            ffma2(acc[t][1], x.u[1], B0.u[1]);
            ffma2(acc[t][2], x.u[0], A1.u[0]);
            ffma2(acc[t][2], x.u[1], B1.u[0]);
            ffma2(acc[t][3], x.u[0], A1.u[1]);
            ffma2(acc[t][3], x.u[1], B1.u[1]);
        }
    }
#pragma unroll
    for (int t = 0; t < 4; ++t)
        res[t] = make_float4(hsum2(acc[t][0]) + bias.x, hsum2(acc[t][1]) + bias.y,
                             hsum2(acc[t][2]) + bias.z, hsum2(acc[t][3]) + bias.w);
}

__global__ void __launch_bounds__(NTHREADS, 1) fused_lane_encoder(
    const float* __restrict__ feat, const float* __restrict__ masks,
    const float* __restrict__ b_emb, const float* __restrict__ g_emb,
    const float* __restrict__ beta_emb,
    const float* __restrict__ b_enc, const float* __restrict__ g_enc,
    const float* __restrict__ beta_enc,
    const float* __restrict__ bq, const float* __restrict__ bk,
    const float* __restrict__ bv,
    const float* __restrict__ ln_g, const float* __restrict__ ln_b,
    float* __restrict__ out)
{
    extern __shared__ float smem[];
    float* hs   = smem;                        // 64*128
    float* qb   = hs + T_ * H_;                // 64*132
    float* kb   = qb + T_ * PITCH4 * 4;
    float* vb   = kb + T_ * PITCH4 * 4;
    float* sval = vb + T_ * PITCH4 * 4;        // 64
    float* pmax = sval + 64;                   // 512

    float4* hs4 = reinterpret_cast<float4*>(hs);
    float4* qb4 = reinterpret_cast<float4*>(qb);
    float4* kb4 = reinterpret_cast<float4*>(kb);
    float4* vb4 = reinterpret_cast<float4*>(vb);

    const int tid  = threadIdx.x;
    const int lane = tid & 31;
    const int wid  = tid >> 5;     // 0..15
    const int t0   = wid * 4;      // this warp's 4 tokens
    const int l    = lane;         // h = 4l..4l+4
    const int blk  = blockIdx.x;

    if (tid < T_) sval[tid] = 1.0f - masks[(size_t)blk * T_ + tid];

    const float4* wemb4 = reinterpret_cast<const float4*>(g_wpk + OFF_EMB);
    const float4* wenc4 = reinterpret_cast<const float4*>(g_wpk + OFF_ENC);

    // ---- Phase 1: emb = relu(LN(feat @ W_emb + b)) ----
    {
        const float4* fg4 = reinterpret_cast<const float4*>(feat + (size_t)blk * T_ * IN_);
        float4 bias = *reinterpret_cast<const float4*>(b_emb + 4 * l);
        float4 gm   = *reinterpret_cast<const float4*>(g_emb + 4 * l);
        float4 bt   = *reinterpret_cast<const float4*>(beta_emb + 4 * l);
        float4 r[4];
        gemm16(wemb4, fg4, t0, l, bias, r);
#pragma unroll
        for (int t = 0; t < 4; ++t) {
            float4 y = ln_warp(r[t], gm, bt);
            hs4[(t0 + t) * 32 + l] = make_float4(fmaxf(y.x, 0.f), fmaxf(y.y, 0.f),
                                                 fmaxf(y.z, 0.f), fmaxf(y.w, 0.f));
        }
        __syncwarp();
    }

    // ---- Phase 2: enc (in place; warp reads/writes only its own rows) ----
    {
        float4 bias = *reinterpret_cast<const float4*>(b_enc + 4 * l);
        float4 gm   = *reinterpret_cast<const float4*>(g_enc + 4 * l);
        float4 bt   = *reinterpret_cast<const float4*>(beta_enc + 4 * l);
        float4 r[4];
        gemm128(wenc4, hs4, t0, l, bias, r);
#pragma unroll
        for (int t = 0; t < 4; ++t) {
            float4 y = ln_warp(r[t], gm, bt);
            hs4[(t0 + t) * 32 + l] = make_float4(fmaxf(y.x, 0.f), fmaxf(y.y, 0.f),
                                                 fmaxf(y.z, 0.f), fmaxf(y.w, 0.f));
        }
        __syncwarp();
    }
    __syncthreads();   // sval visible; hs settled for attention epoch

    const float vk1 = sval[lane];
    const float vk2 = sval[lane + 32];
    const int hsel = lane >> 4;

    // ---- Phase 3: transformer layers ----
    for (int d = 0; d < DEPTH_; ++d) {
        {
            float4 r[4];
            float4 bias = *reinterpret_cast<const float4*>(bq + d * H_ + 4 * l);
            gemm128(reinterpret_cast<const float4*>(g_wpk + off_qkv(d, 0)), hs4, t0, l, bias, r);
#pragma unroll
            for (int t = 0; t < 4; ++t) qb4[(t0 + t) * PITCH4 + l] = r[t];
            bias = *reinterpret_cast<const float4*>(bk + d * H_ + 4 * l);
            gemm128(reinterpret_cast<const float4*>(g_wpk + off_qkv(d, 1)), hs4, t0, l, bias, r);
#pragma unroll
            for (int t = 0; t < 4; ++t) kb4[(t0 + t) * PITCH4 + l] = r[t];
            bias = *reinterpret_cast<const float4*>(bv + d * H_ + 4 * l);
            gemm128(reinterpret_cast<const float4*>(g_wpk + off_qkv(d, 2)), hs4, t0, l, bias, r);
#pragma unroll
            for (int t = 0; t < 4; ++t) vb4[(t0 + t) * PITCH4 + l] = r[t];
        }
        __syncthreads();

        // ---- attention: warp owns queries t0..t0+3 ----
        float p1[2][4], p2[2][4];   // [head][query]; this lane's keys = lane, lane+32
#pragma unroll
        for (int head = 0; head < 2; ++head) {
            const int base = head * 16;
            u64 s1[4] = {}, s2[4] = {};
#pragma unroll 4
            for (int c = 0; c < 16; ++c) {
                F4 k1; k1.v = kb4[lane * PITCH4 + base + c];
                F4 k2; k2.v = kb4[(lane + 32) * PITCH4 + base + c];
#pragma unroll
                for (int qq = 0; qq < 4; ++qq) {
                    F4 q; q.v = qb4[(t0 + qq) * PITCH4 + base + c];
                    ffma2(s1[qq], q.u[0], k1.u[0]);
                    ffma2(s1[qq], q.u[1], k1.u[1]);
                    ffma2(s2[qq], q.u[0], k2.u[0]);
                    ffma2(s2[qq], q.u[1], k2.u[1]);
                }
            }
#pragma unroll
            for (int qq = 0; qq < 4; ++qq) {
                float vq = sval[t0 + qq];
                float sc1 = hsum2(s1[qq]) * 0.125f + (1.f - vq * vk1) * -10000.f;
                float sc2 = hsum2(s2[qq]) * 0.125f + (1.f - vq * vk2) * -10000.f;
                float mx = warp_max(fmaxf(sc1, sc2));
                float e1 = __expf(sc1 - mx), e2 = __expf(sc2 - mx);
                float inv = 1.f / warp_sum(e1 + e2);
                p1[head][qq] = e1 * inv;
                p2[head][qq] = e2 * inv;
            }
        }

        // ctx: lane owns output dims 4l..4l+4 (head = lane/16)
        u64 ca[4] = {}, cb[4] = {};
#pragma unroll 4
        for (int j = 0; j < 32; ++j) {
            F4 v; v.v = vb4[j * PITCH4 + lane];
#pragma unroll
            for (int qq = 0; qq < 4; ++qq) {
                float pj0 = __shfl_sync(0xffffffffu, p1[0][qq], j);
                float pj1 = __shfl_sync(0xffffffffu, p1[1][qq], j);
                u64 pp = pk2(hsel ? pj1 : pj0, hsel ? pj1 : pj0);
                ffma2(ca[qq], pp, v.u[0]);
                ffma2(cb[qq], pp, v.u[1]);
            }
        }
#pragma unroll 4
        for (int j = 0; j < 32; ++j) {
            F4 v; v.v = vb4[(j + 32) * PITCH4 + lane];
#pragma unroll
            for (int qq = 0; qq < 4; ++qq) {
                float pj0 = __shfl_sync(0xffffffffu, p2[0][qq], j);
                float pj1 = __shfl_sync(0xffffffffu, p2[1][qq], j);
                u64 pp = pk2(hsel ? pj1 : pj0, hsel ? pj1 : pj0);
                ffma2(ca[qq], pp, v.u[0]);
                ffma2(cb[qq], pp, v.u[1]);
            }
        }

        // residual + LN (warp-local, ctx still in registers)
        {
            float4 gm = *reinterpret_cast<const float4*>(ln_g + d * H_ + 4 * l);
            float4 bt = *reinterpret_cast<const float4*>(ln_b + d * H_ + 4 * l);
#pragma unroll
            for (int qq = 0; qq < 4; ++qq) {
                int t = t0 + qq;
                float c0, c1;
                asm("mov.b64 {%0, %1}, %2;" : "=f"(c0), "=f"(c1) : "l"(ca[qq]));
                float c2, c3;
                asm("mov.b64 {%0, %1}, %2;" : "=f"(c2), "=f"(c3) : "l"(cb[qq]));
                float4 hv = hs4[t * 32 + l];
                float4 x = make_float4(fmaxf(c0, 0.f) + hv.x, fmaxf(c1, 0.f) + hv.y,
                                       fmaxf(c2, 0.f) + hv.z, fmaxf(c3, 0.f) + hv.w);
                hs4[t * 32 + l] = ln_warp(x, gm, bt);
            }
        }
        __syncthreads();
    }

    // ---- Phase 4: max over T ----
    {
        const int part = tid >> 7;          // 0..3
        const int hh   = tid & 127;
        float m = -3.4e38f;
#pragma unroll
        for (int t = 0; t < 16; ++t)
            m = fmaxf(m, hs[(part * 16 + t) * H_ + hh]);
        pmax[part * H_ + hh] = m;
    }
    __syncthreads();
    if (tid < H_)
        out[(size_t)blk * H_ + tid] = fmaxf(fmaxf(pmax[tid], pmax[H_ + tid]),
                                            fmaxf(pmax[2 * H_ + tid], pmax[3 * H_ + tid]));
}

} // namespace

extern "C" void kernel_launch(void* const* d_in, const int* in_sizes, int n_in,
                              void* d_out, int out_size) {
    const float* feat     = (const float*)d_in[0];
    const float* masks    = (const float*)d_in[1];
    const float* W_emb    = (const float*)d_in[2];
    const float* b_emb    = (const float*)d_in[3];
    const float* g_emb    = (const float*)d_in[4];
    const float* beta_emb = (const float*)d_in[5];
    const float* W_enc    = (const float*)d_in[6];
    const float* b_enc    = (const float*)d_in[7];
    const float* g_enc    = (const float*)d_in[8];
    const float* beta_enc = (const float*)d_in[9];
    const float* Wq       = (const float*)d_in[10];
    const float* bq       = (const float*)d_in[11];
    const float* Wk       = (const float*)d_in[12];
    const float* bk       = (const float*)d_in[13];
    const float* Wv       = (const float*)d_in[14];
    const float* bv       = (const float*)d_in[15];
    const float* ln_g     = (const float*)d_in[16];
    const float* ln_b     = (const float*)d_in[17];
    float* out = (float*)d_out;

    int nseq = in_sizes[0] / (T_ * IN_);

    pack_weights<<<(WPK_TOTAL + 255) / 256, 256>>>(W_emb, W_enc, Wq, Wk, Wv);

    size_t smem = (size_t)(T_ * H_ + 3 * T_ * PITCH4 * 4 + 64 + 512) * sizeof(float);
    cudaFuncSetAttribute(fused_lane_encoder,
                         cudaFuncAttributeMaxDynamicSharedMemorySize, (int)smem);
    fused_lane_encoder<<<nseq, NTHREADS, smem>>>(
        feat, masks, b_emb, g_emb, beta_emb, b_enc, g_enc, beta_enc,
        bq, bk, bv, ln_g, ln_b, out);
}

// round 6
// speedup vs baseline: 1.4909x; 1.0022x over previous
#include <cuda_runtime.h>

namespace {

typedef unsigned long long u64;

constexpr int T_ = 64;
constexpr int IN_ = 16;
constexpr int H_ = 128;
constexpr int DEPTH_ = 3;
constexpr int PITCH4 = 33;          // float4 row pitch for Q/K/V buffers (132 floats)
constexpr float EPS = 1e-5f;
constexpr int NTHREADS = 512;

// ---------------- packed weights in global scratch ----------------
// g_wpk[row*128 + h] = (W[2*m][h], W[2*m+1][h])  (k-pair packing)
// rows: emb 8 | enc 64 | (Wq,Wk,Wv) x 3 layers, 64 each
constexpr int ROWS_EMB = 8;
constexpr int ROWS_MAT = 64;
constexpr int OFF_EMB = 0;
constexpr int OFF_ENC = ROWS_EMB * 128;
__host__ __device__ constexpr int off_qkv(int d, int w) {
    return (ROWS_EMB + ROWS_MAT + (d * 3 + w) * ROWS_MAT) * 128;
}
constexpr int WPK_TOTAL = (ROWS_EMB + ROWS_MAT + 9 * ROWS_MAT) * 128;

__device__ float2 g_wpk[WPK_TOTAL];

__global__ void pack_weights(const float* __restrict__ W_emb,
                             const float* __restrict__ W_enc,
                             const float* __restrict__ Wq,
                             const float* __restrict__ Wk,
                             const float* __restrict__ Wv) {
    int i = blockIdx.x * 256 + threadIdx.x;
    if (i >= WPK_TOTAL) return;
    int h = i & 127;
    int row = i >> 7;
    const float* src;
    int m;
    if (row < ROWS_EMB) { src = W_emb; m = row; }
    else if (row < ROWS_EMB + ROWS_MAT) { src = W_enc; m = row - ROWS_EMB; }
    else {
        int r = row - (ROWS_EMB + ROWS_MAT);
        int mat = r >> 6; m = r & 63;
        int d = mat / 3, w = mat % 3;
        src = (w == 0 ? Wq : (w == 1 ? Wk : Wv)) + d * H_ * H_;
    }
    g_wpk[i] = make_float2(src[(2 * m) * H_ + h], src[(2 * m + 1) * H_ + h]);
}

// ---------------- f32x2 helpers ----------------
union F4 { float4 v; u64 u[2]; };

__device__ __forceinline__ void ffma2(u64& d, u64 a, u64 b) {
    asm("fma.rn.f32x2 %0, %1, %2, %0;" : "+l"(d) : "l"(a), "l"(b));
}
__device__ __forceinline__ u64 pk2(float lo, float hi) {
    u64 r; asm("mov.b64 %0, {%1, %2};" : "=l"(r) : "f"(lo), "f"(hi)); return r;
}
__device__ __forceinline__ float hsum2(u64 v) {
    float lo, hi; asm("mov.b64 {%0, %1}, %2;" : "=f"(lo), "=f"(hi) : "l"(v));
    return lo + hi;
}

__device__ __forceinline__ float warp_sum(float v) {
#pragma unroll
    for (int o = 16; o > 0; o >>= 1) v += __shfl_xor_sync(0xffffffffu, v, o);
    return v;
}
__device__ __forceinline__ float warp_max(float v) {
#pragma unroll
    for (int o = 16; o > 0; o >>= 1) v = fmaxf(v, __shfl_xor_sync(0xffffffffu, v, o));
    return v;
}

// warp-local layernorm over H=128 (32 lanes x 4 values)
__device__ __forceinline__ float4 ln_warp(float4 x, float4 gm, float4 bt) {
    float s  = warp_sum(x.x + x.y + x.z + x.w);
    float ss = warp_sum(x.x * x.x + x.y * x.y + x.z * x.z + x.w * x.w);
    float mean = s * (1.f / H_);
    float var  = ss * (1.f / H_) - mean * mean;
    float inv  = rsqrtf(var + EPS);
    return make_float4(gm.x * (x.x - mean) * inv + bt.x,
                       gm.y * (x.y - mean) * inv + bt.y,
                       gm.z * (x.z - mean) * inv + bt.z,
                       gm.w * (x.w - mean) * inv + bt.w);
}

// res[t] (float4, h = 4l..4l+4) = bias + x[t] @ W, K=128, for 4 tokens t0..t0+3.
__device__ __forceinline__ void gemm128(const float4* __restrict__ wp4,
                                        const float4* __restrict__ x4,
                                        int t0, int l, float4 bias, float4 res[4]) {
    u64 acc[4][4] = {};
#pragma unroll 2
    for (int kb = 0; kb < 32; ++kb) {
        const float4* w0 = wp4 + (2 * kb) * 64 + 2 * l;
        const float4* w1 = wp4 + (2 * kb + 1) * 64 + 2 * l;
        F4 A0, A1, B0, B1;
        A0.v = w0[0]; A1.v = w0[1];
        B0.v = w1[0]; B1.v = w1[1];
#pragma unroll
        for (int t = 0; t < 4; ++t) {
            F4 x; x.v = x4[(t0 + t) * 32 + kb];
            ffma2(acc[t][0], x.u[0], A0.u[0]);
            ffma2(acc[t][0], x.u[1], B0.u[0]);
            ffma2(acc[t][1], x.u[0], A0.u[1]);
            ffma2(acc[t][1], x.u[1], B0.u[1]);
            ffma2(acc[t][2], x.u[0], A1.u[0]);
            ffma2(acc[t][2], x.u[1], B1.u[0]);
            ffma2(acc[t][3], x.u[0], A1.u[1]);
            ffma2(acc[t][3], x.u[1], B1.u[1]);
        }
    }
#pragma unroll
    for (int t = 0; t < 4; ++t)
        res[t] = make_float4(hsum2(acc[t][0]) + bias.x, hsum2(acc[t][1]) + bias.y,
                             hsum2(acc[t][2]) + bias.z, hsum2(acc[t][3]) + bias.w);
}

// K = 16 variant (emb), x read from global
__device__ __forceinline__ void gemm16(const float4* __restrict__ wp4,
                                       const float4* __restrict__ xg4,
                                       int t0, int l, float4 bias, float4 res[4]) {
    u64 acc[4][4] = {};
#pragma unroll
    for (int kb = 0; kb < 4; ++kb) {
        const float4* w0 = wp4 + (2 * kb) * 64 + 2 * l;
        const float4* w1 = wp4 + (2 * kb + 1) * 64 + 2 * l;
        F4 A0, A1, B0, B1;
        A0.v = w0[0]; A1.v = w0[1];
        B0.v = w1[0]; B1.v = w1[1];
#pragma unroll
        for (int t = 0; t < 4; ++t) {
            F4 x; x.v = xg4[(t0 + t) * 4 + kb];
            ffma2(acc[t][0], x.u[0], A0.u[0]);
            ffma2(acc[t][0], x.u[1], B0.u[0]);
            ffma2(acc[t][1], x.u[0], A0.u[1]);
            ffma2(acc[t][1], x.u[1], B0.u[1]);
            ffma2(acc[t][2], x.u[0], A1.u[0]);
            ffma2(acc[t][2], x.u[1], B1.u[0]);
            ffma2(acc[t][3], x.u[0], A1.u[1]);
            ffma2(acc[t][3], x.u[1], B1.u[1]);
        }
    }
#pragma unroll
    for (int t = 0; t < 4; ++t)
        res[t] = make_float4(hsum2(acc[t][0]) + bias.x, hsum2(acc[t][1]) + bias.y,
                             hsum2(acc[t][2]) + bias.z, hsum2(acc[t][3]) + bias.w);
}

__global__ void __launch_bounds__(NTHREADS, 1) fused_lane_encoder(
    const float* __restrict__ feat, const float* __restrict__ masks,
    const float* __restrict__ b_emb, const float* __restrict__ g_emb,
    const float* __restrict__ beta_emb,
    const float* __restrict__ b_enc, const float* __restrict__ g_enc,
    const float* __restrict__ beta_enc,
    const float* __restrict__ bq, const float* __restrict__ bk,
    const float* __restrict__ bv,
    const float* __restrict__ ln_g, const float* __restrict__ ln_b,
    float* __restrict__ out)
{
    extern __shared__ float smem[];
    float* hs   = smem;                        // 64*128
    float* qb   = hs + T_ * H_;                // 64*132
    float* kb   = qb + T_ * PITCH4 * 4;
    float* vb   = kb + T_ * PITCH4 * 4;
    float* sval = vb + T_ * PITCH4 * 4;        // 64
    float* pmax = sval + 64;                   // 512

    float4* hs4 = reinterpret_cast<float4*>(hs);
    float4* qb4 = reinterpret_cast<float4*>(qb);
    float4* kb4 = reinterpret_cast<float4*>(kb);
    float4* vb4 = reinterpret_cast<float4*>(vb);

    const int tid  = threadIdx.x;
    const int lane = tid & 31;
    const int wid  = tid >> 5;     // 0..15
    const int t0   = wid * 4;      // this warp's 4 tokens
    const int l    = lane;         // h = 4l..4l+4
    const int blk  = blockIdx.x;

    if (tid < T_) sval[tid] = 1.0f - masks[(size_t)blk * T_ + tid];

    const float4* wemb4 = reinterpret_cast<const float4*>(g_wpk + OFF_EMB);
    const float4* wenc4 = reinterpret_cast<const float4*>(g_wpk + OFF_ENC);

    // ---- Phase 1: emb = relu(LN(feat @ W_emb + b)) ----
    {
        const float4* fg4 = reinterpret_cast<const float4*>(feat + (size_t)blk * T_ * IN_);
        float4 bias = *reinterpret_cast<const float4*>(b_emb + 4 * l);
        float4 gm   = *reinterpret_cast<const float4*>(g_emb + 4 * l);
        float4 bt   = *reinterpret_cast<const float4*>(beta_emb + 4 * l);
        float4 r[4];
        gemm16(wemb4, fg4, t0, l, bias, r);
#pragma unroll
        for (int t = 0; t < 4; ++t) {
            float4 y = ln_warp(r[t], gm, bt);
            hs4[(t0 + t) * 32 + l] = make_float4(fmaxf(y.x, 0.f), fmaxf(y.y, 0.f),
                                                 fmaxf(y.z, 0.f), fmaxf(y.w, 0.f));
        }
        __syncwarp();
    }

    // ---- Phase 2: enc (in place; warp reads/writes only its own rows) ----
    {
        float4 bias = *reinterpret_cast<const float4*>(b_enc + 4 * l);
        float4 gm   = *reinterpret_cast<const float4*>(g_enc + 4 * l);
        float4 bt   = *reinterpret_cast<const float4*>(beta_enc + 4 * l);
        float4 r[4];
        gemm128(wenc4, hs4, t0, l, bias, r);
#pragma unroll
        for (int t = 0; t < 4; ++t) {
            float4 y = ln_warp(r[t], gm, bt);
            hs4[(t0 + t) * 32 + l] = make_float4(fmaxf(y.x, 0.f), fmaxf(y.y, 0.f),
                                                 fmaxf(y.z, 0.f), fmaxf(y.w, 0.f));
        }
        __syncwarp();
    }
    __syncthreads();   // sval visible; hs settled for attention epoch

    const float vk1 = sval[lane];
    const float vk2 = sval[lane + 32];
    const int hsel = lane >> 4;

    // ---- Phase 3: transformer layers ----
    for (int d = 0; d < DEPTH_; ++d) {
        {
            float4 r[4];
            float4 bias = *reinterpret_cast<const float4*>(bq + d * H_ + 4 * l);
            gemm128(reinterpret_cast<const float4*>(g_wpk + off_qkv(d, 0)), hs4, t0, l, bias, r);
#pragma unroll
            for (int t = 0; t < 4; ++t) qb4[(t0 + t) * PITCH4 + l] = r[t];
            bias = *reinterpret_cast<const float4*>(bk + d * H_ + 4 * l);
            gemm128(reinterpret_cast<const float4*>(g_wpk + off_qkv(d, 1)), hs4, t0, l, bias, r);
#pragma unroll
            for (int t = 0; t < 4; ++t) kb4[(t0 + t) * PITCH4 + l] = r[t];
            bias = *reinterpret_cast<const float4*>(bv + d * H_ + 4 * l);
            gemm128(reinterpret_cast<const float4*>(g_wpk + off_qkv(d, 2)), hs4, t0, l, bias, r);
#pragma unroll
            for (int t = 0; t < 4; ++t) vb4[(t0 + t) * PITCH4 + l] = r[t];
        }
        __syncthreads();

        // ---- attention: warp owns queries t0..t0+3 ----
        float p1[2][4], p2[2][4];   // [head][query]; this lane's keys = lane, lane+32
#pragma unroll
        for (int head = 0; head < 2; ++head) {
            const int base = head * 16;
            u64 s1[4] = {}, s2[4] = {};
#pragma unroll 4
            for (int c = 0; c < 16; ++c) {
                F4 k1; k1.v = kb4[lane * PITCH4 + base + c];
                F4 k2; k2.v = kb4[(lane + 32) * PITCH4 + base + c];
#pragma unroll
                for (int qq = 0; qq < 4; ++qq) {
                    F4 q; q.v = qb4[(t0 + qq) * PITCH4 + base + c];
                    ffma2(s1[qq], q.u[0], k1.u[0]);
                    ffma2(s1[qq], q.u[1], k1.u[1]);
                    ffma2(s2[qq], q.u[0], k2.u[0]);
                    ffma2(s2[qq], q.u[1], k2.u[1]);
                }
            }
#pragma unroll
            for (int qq = 0; qq < 4; ++qq) {
                float vq = sval[t0 + qq];
                float sc1 = hsum2(s1[qq]) * 0.125f + (1.f - vq * vk1) * -10000.f;
                float sc2 = hsum2(s2[qq]) * 0.125f + (1.f - vq * vk2) * -10000.f;
                float mx = warp_max(fmaxf(sc1, sc2));
                float e1 = __expf(sc1 - mx), e2 = __expf(sc2 - mx);
                float inv = 1.f / warp_sum(e1 + e2);
                p1[head][qq] = e1 * inv;
                p2[head][qq] = e2 * inv;
            }
        }

        // ctx: lane owns output dims 4l..4l+4 (head = lane/16)
        u64 ca[4] = {}, cb[4] = {};
#pragma unroll 4
        for (int j = 0; j < 32; ++j) {
            F4 v; v.v = vb4[j * PITCH4 + lane];
#pragma unroll
            for (int qq = 0; qq < 4; ++qq) {
                float pj0 = __shfl_sync(0xffffffffu, p1[0][qq], j);
                float pj1 = __shfl_sync(0xffffffffu, p1[1][qq], j);
                u64 pp = pk2(hsel ? pj1 : pj0, hsel ? pj1 : pj0);
                ffma2(ca[qq], pp, v.u[0]);
                ffma2(cb[qq], pp, v.u[1]);
            }
        }
#pragma unroll 4
        for (int j = 0; j < 32; ++j) {
            F4 v; v.v = vb4[(j + 32) * PITCH4 + lane];
#pragma unroll
            for (int qq = 0; qq < 4; ++qq) {
                float pj0 = __shfl_sync(0xffffffffu, p2[0][qq], j);
                float pj1 = __shfl_sync(0xffffffffu, p2[1][qq], j);
                u64 pp = pk2(hsel ? pj1 : pj0, hsel ? pj1 : pj0);
                ffma2(ca[qq], pp, v.u[0]);
                ffma2(cb[qq], pp, v.u[1]);
            }
        }

        // residual + LN (warp-local, ctx still in registers)
        {
            float4 gm = *reinterpret_cast<const float4*>(ln_g + d * H_ + 4 * l);
            float4 bt = *reinterpret_cast<const float4*>(ln_b + d * H_ + 4 * l);
#pragma unroll
            for (int qq = 0; qq < 4; ++qq) {
                int t = t0 + qq;
                float c0, c1;
                asm("mov.b64 {%0, %1}, %2;" : "=f"(c0), "=f"(c1) : "l"(ca[qq]));
                float c2, c3;
                asm("mov.b64 {%0, %1}, %2;" : "=f"(c2), "=f"(c3) : "l"(cb[qq]));
                float4 hv = hs4[t * 32 + l];
                float4 x = make_float4(fmaxf(c0, 0.f) + hv.x, fmaxf(c1, 0.f) + hv.y,
                                       fmaxf(c2, 0.f) + hv.z, fmaxf(c3, 0.f) + hv.w);
                hs4[t * 32 + l] = ln_warp(x, gm, bt);
            }
        }
        __syncthreads();
    }

    // ---- Phase 4: max over T ----
    {
        const int part = tid >> 7;          // 0..3
        const int hh   = tid & 127;
        float m = -3.4e38f;
#pragma unroll
        for (int t = 0; t < 16; ++t)
            m = fmaxf(m, hs[(part * 16 + t) * H_ + hh]);
        pmax[part * H_ + hh] = m;
    }
    __syncthreads();
    if (tid < H_)
        out[(size_t)blk * H_ + tid] = fmaxf(fmaxf(pmax[tid], pmax[H_ + tid]),
                                            fmaxf(pmax[2 * H_ + tid], pmax[3 * H_ + tid]));
}

} // namespace

extern "C" void kernel_launch(void* const* d_in, const int* in_sizes, int n_in,
                              void* d_out, int out_size) {
    const float* feat     = (const float*)d_in[0];
    const float* masks    = (const float*)d_in[1];
    const float* W_emb    = (const float*)d_in[2];
    const float* b_emb    = (const float*)d_in[3];
    const float* g_emb    = (const float*)d_in[4];
    const float* beta_emb = (const float*)d_in[5];
    const float* W_enc    = (const float*)d_in[6];
    const float* b_enc    = (const float*)d_in[7];
    const float* g_enc    = (const float*)d_in[8];
    const float* beta_enc = (const float*)d_in[9];
    const float* Wq       = (const float*)d_in[10];
    const float* bq       = (const float*)d_in[11];
    const float* Wk       = (const float*)d_in[12];
    const float* bk       = (const float*)d_in[13];
    const float* Wv       = (const float*)d_in[14];
    const float* bv       = (const float*)d_in[15];
    const float* ln_g     = (const float*)d_in[16];
    const float* ln_b     = (const float*)d_in[17];
    float* out = (float*)d_out;

    int nseq = in_sizes[0] / (T_ * IN_);

    pack_weights<<<(WPK_TOTAL + 255) / 256, 256>>>(W_emb, W_enc, Wq, Wk, Wv);

    size_t smem = (size_t)(T_ * H_ + 3 * T_ * PITCH4 * 4 + 64 + 512) * sizeof(float);
    cudaFuncSetAttribute(fused_lane_encoder,
                         cudaFuncAttributeMaxDynamicSharedMemorySize, (int)smem);
    fused_lane_encoder<<<nseq, NTHREADS, smem>>>(
        feat, masks, b_emb, g_emb, beta_emb, b_enc, g_enc, beta_enc,
        bq, bk, bv, ln_g, ln_b, out);
}

// round 13
// speedup vs baseline: 3.1942x; 2.1425x over previous
#include <cuda_runtime.h>
#include <cuda_bf16.h>

namespace {

typedef unsigned long long u64;
typedef unsigned int u32;

constexpr int IN_ = 16;
constexpr int H_ = 128;
constexpr int NT = 512;
constexpr float EPS = 1e-5f;
constexpr int P4 = 33;            // float4 pitch (132 floats) for q/k/v buffers
constexpr int ASTR = 68;          // ahl row stride in b32 words (64 data + 4 pad; 68%32=4 -> conflict-free)
constexpr int APL = 64 * ASTR;    // ahl plane size (hi -> lo offset), b32 words

// B fragments packed for mma.m16n8k16: [mat 0..9][split 0..1][kt 0..7][nt 0..15][lane][2 u32]
// mat: 0 = enc, 1+3d+{0,1,2} = Wq/Wk/Wv of layer d
constexpr int BW_U32 = 10 * 2 * 8 * 16 * 32 * 2;   // 163840
__device__ __align__(16) u32 g_bw[BW_U32];
__device__ __align__(16) float2 g_wemb[8 * 128];

__device__ __forceinline__ u32 bfpair(float lo, float hi) {
    u32 r; asm("cvt.rn.bf16x2.f32 %0, %1, %2;" : "=r"(r) : "f"(hi), "f"(lo)); return r;
}

__global__ void pack_emb(const float* __restrict__ W) {
    int i = blockIdx.x * 256 + threadIdx.x;
    if (i >= 1024) return;
    int h = i & 127, m = i >> 7;
    g_wemb[i] = make_float2(W[(2 * m) * H_ + h], W[(2 * m + 1) * H_ + h]);
}

__global__ void pack_bw(const float* __restrict__ We, const float* __restrict__ Wq,
                        const float* __restrict__ Wk, const float* __restrict__ Wv) {
    int i = blockIdx.x * 256 + threadIdx.x;
    if (i >= BW_U32) return;
    int reg  = i & 1;
    int lane = (i >> 1) & 31;
    int nt   = (i >> 6) & 15;
    int kt   = (i >> 10) & 7;
    int s    = (i >> 13) & 1;
    int m    = i >> 14;
    const float* src;
    if (m == 0) src = We;
    else { int r = m - 1, d = r / 3, w = r % 3;
           src = (w == 0 ? Wq : (w == 1 ? Wk : Wv)) + d * H_ * H_; }
    int k0 = kt * 16 + (lane & 3) * 2 + reg * 8;
    int n  = nt * 8 + (lane >> 2);
    float x0 = src[k0 * H_ + n], x1 = src[(k0 + 1) * H_ + n];
    if (s) {
        x0 = x0 - __bfloat162float(__float2bfloat16(x0));
        x1 = x1 - __bfloat162float(__float2bfloat16(x1));
    }
    g_bw[i] = bfpair(x0, x1);
}

// ---------------- scalar helpers (proven) ----------------
union F4 { float4 v; u64 u[2]; };
__device__ __forceinline__ void ffma2(u64& d, u64 a, u64 b) {
    asm("fma.rn.f32x2 %0, %1, %2, %0;" : "+l"(d) : "l"(a), "l"(b));
}
__device__ __forceinline__ u64 pk2(float lo, float hi) {
    u64 r; asm("mov.b64 %0, {%1, %2};" : "=l"(r) : "f"(lo), "f"(hi)); return r;
}
__device__ __forceinline__ float hsum2(u64 v) {
    float lo, hi; asm("mov.b64 {%0, %1}, %2;" : "=f"(lo), "=f"(hi) : "l"(v));
    return lo + hi;
}
__device__ __forceinline__ float warp_sum(float v) {
#pragma unroll
    for (int o = 16; o > 0; o >>= 1) v += __shfl_xor_sync(0xffffffffu, v, o);
    return v;
}
__device__ __forceinline__ float warp_max(float v) {
#pragma unroll
    for (int o = 16; o > 0; o >>= 1) v = fmaxf(v, __shfl_xor_sync(0xffffffffu, v, o));
    return v;
}
__device__ __forceinline__ float4 ln_warp(float4 x, float4 gm, float4 bt) {
    float s  = warp_sum(x.x + x.y + x.z + x.w);
    float ss = warp_sum(x.x * x.x + x.y * x.y + x.z * x.z + x.w * x.w);
    float mean = s * (1.f / H_);
    float inv  = rsqrtf(ss * (1.f / H_) - mean * mean + EPS);
    return make_float4(gm.x * (x.x - mean) * inv + bt.x, gm.y * (x.y - mean) * inv + bt.y,
                       gm.z * (x.z - mean) * inv + bt.z, gm.w * (x.w - mean) * inv + bt.w);
}

// write bf16 hi/lo planes of one row-slice (cols 4l..4l+3) of ahl
__device__ __forceinline__ void store_ahl(u32* __restrict__ ahl, int row, int l, float4 y) {
    u32 h0 = bfpair(y.x, y.y), h1 = bfpair(y.z, y.w);
    float dx = y.x - __bfloat162float(__float2bfloat16(y.x));
    float dy = y.y - __bfloat162float(__float2bfloat16(y.y));
    float dz = y.z - __bfloat162float(__float2bfloat16(y.z));
    float dw = y.w - __bfloat162float(__float2bfloat16(y.w));
    u32 l0 = bfpair(dx, dy), l1 = bfpair(dz, dw);
    *reinterpret_cast<u64*>(ahl + row * ASTR + 2 * l)       = (u64)h0 | ((u64)h1 << 32);
    *reinterpret_cast<u64*>(ahl + APL + row * ASTR + 2 * l) = (u64)l0 | ((u64)l1 << 32);
}

#define HMMA(d, a0, a1, a2, a3, b0, b1) \
    asm volatile("mma.sync.aligned.m16n8k16.row.col.f32.bf16.bf16.f32 " \
        "{%0,%1,%2,%3},{%4,%5,%6,%7},{%8,%9},{%0,%1,%2,%3};" \
        : "+f"((d)[0]), "+f"((d)[1]), "+f"((d)[2]), "+f"((d)[3]) \
        : "r"(a0), "r"(a1), "r"(a2), "r"(a3), "r"(b0), "r"(b1))

// one 64x128x128 GEMM tile-slice for this warp: acc[nt_local][4]
__device__ __forceinline__ void gemm_mma(const u32* __restrict__ ahl,
                                         const u64* __restrict__ bw,  // matrix base (hi plane), u64 units
                                         int mt, int ng, int lane, float acc[4][4]) {
#pragma unroll
    for (int j = 0; j < 4; ++j)
#pragma unroll
        for (int r = 0; r < 4; ++r) acc[j][r] = 0.f;
    const int rb = (mt * 16 + (lane >> 2)) * ASTR;
#pragma unroll
    for (int kt = 0; kt < 8; ++kt) {
        const int ca = kt * 8 + (lane & 3);
        u32 ah0 = ahl[rb + ca],             ah1 = ahl[rb + 8 * ASTR + ca];
        u32 ah2 = ahl[rb + ca + 4],         ah3 = ahl[rb + 8 * ASTR + ca + 4];
        u32 al0 = ahl[APL + rb + ca],       al1 = ahl[APL + rb + 8 * ASTR + ca];
        u32 al2 = ahl[APL + rb + ca + 4],   al3 = ahl[APL + rb + 8 * ASTR + ca + 4];
#pragma unroll
        for (int j = 0; j < 4; ++j) {
            const int nt = ng * 4 + j;
            u64 bh = bw[(kt * 16 + nt) * 32 + lane];
            u64 bl = bw[4096 + (kt * 16 + nt) * 32 + lane];
            u32 bh0 = (u32)bh, bh1 = (u32)(bh >> 32);
            u32 bl0 = (u32)bl, bl1 = (u32)(bl >> 32);
            HMMA(acc[j], ah0, ah1, ah2, ah3, bh0, bh1);
            HMMA(acc[j], al0, al1, al2, al3, bh0, bh1);
            HMMA(acc[j], ah0, ah1, ah2, ah3, bl0, bl1);
        }
    }
}

// scatter D tile (+bias) into pitched fp32 buffer (132-float rows)
__device__ __forceinline__ void store_tile(float* __restrict__ buf,
                                           const float* __restrict__ biasg,
                                           int mt, int ng, int lane, float acc[4][4]) {
    const int g = lane >> 2, q = lane & 3;
#pragma unroll
    for (int j = 0; j < 4; ++j) {
        const int c = ng * 32 + j * 8 + q * 2;
        float2 bv = *reinterpret_cast<const float2*>(biasg + c);
        const int r = mt * 16 + g;
        *reinterpret_cast<float2*>(buf + r * 132 + c) =
            make_float2(acc[j][0] + bv.x, acc[j][1] + bv.y);
        *reinterpret_cast<float2*>(buf + (r + 8) * 132 + c) =
            make_float2(acc[j][2] + bv.x, acc[j][3] + bv.y);
    }
}

// K=16 emb gemm, 4 tokens, x from global (proven)
__device__ __forceinline__ void gemm16(const float4* __restrict__ wp4,
                                       const float4* __restrict__ xg4,
                                       int t0, int l, float4 bias, float4 res[4]) {
    u64 acc[4][4] = {};
#pragma unroll
    for (int kb = 0; kb < 4; ++kb) {
        const float4* w0 = wp4 + (2 * kb) * 64 + 2 * l;
        const float4* w1 = wp4 + (2 * kb + 1) * 64 + 2 * l;
        F4 A0, A1, B0, B1;
        A0.v = w0[0]; A1.v = w0[1]; B0.v = w1[0]; B1.v = w1[1];
#pragma unroll
        for (int t = 0; t < 4; ++t) {
            F4 x; x.v = xg4[(t0 + t) * 4 + kb];
            ffma2(acc[t][0], x.u[0], A0.u[0]); ffma2(acc[t][0], x.u[1], B0.u[0]);
            ffma2(acc[t][1], x.u[0], A0.u[1]); ffma2(acc[t][1], x.u[1], B0.u[1]);
            ffma2(acc[t][2], x.u[0], A1.u[0]); ffma2(acc[t][2], x.u[1], B1.u[0]);
            ffma2(acc[t][3], x.u[0], A1.u[1]); ffma2(acc[t][3], x.u[1], B1.u[1]);
        }
    }
#pragma unroll
    for (int t = 0; t < 4; ++t)
        res[t] = make_float4(hsum2(acc[t][0]) + bias.x, hsum2(acc[t][1]) + bias.y,
                             hsum2(acc[t][2]) + bias.z, hsum2(acc[t][3]) + bias.w);
}

// ================= main fused kernel: 1 sequence per CTA =================
__global__ void __launch_bounds__(NT, 1) fused_lane_encoder(
    const float* __restrict__ feat, const float* __restrict__ masks,
    const float* __restrict__ b_emb, const float* __restrict__ g_emb,
    const float* __restrict__ beta_emb,
    const float* __restrict__ b_enc, const float* __restrict__ g_enc,
    const float* __restrict__ beta_enc,
    const float* __restrict__ bq, const float* __restrict__ bk,
    const float* __restrict__ bv,
    const float* __restrict__ ln_g, const float* __restrict__ ln_b,
    float* __restrict__ out)
{
    extern __shared__ float smem[];
    float* const qb   = smem;                 // 64*132
    float* const kb   = qb + 64 * 132;
    float* const vb   = kb + 64 * 132;
    float* const hs   = vb + 64 * 132;        // 64*128 fp32
    u32*   const ahl  = reinterpret_cast<u32*>(hs + 64 * 128);  // 2*64*68 u32
    float* const sval = reinterpret_cast<float*>(ahl + 2 * APL); // 64

    float4* const hs4 = reinterpret_cast<float4*>(hs);
    float4* const qb4 = reinterpret_cast<float4*>(qb);
    float4* const kb4 = reinterpret_cast<float4*>(kb);
    float4* const vb4 = reinterpret_cast<float4*>(vb);

    const int tid  = threadIdx.x;
    const int lane = tid & 31;
    const int wid  = tid >> 5;       // 0..15
    const int mt   = wid & 3;        // M-tile (16 rows)
    const int ng   = wid >> 2;       // N-group (32 cols)
    const int blk  = blockIdx.x;

    if (tid < 64) sval[tid] = 1.0f - masks[(size_t)blk * 64 + tid];

    // ---- Phase 1: emb = relu(LN(feat @ W_emb + b)); warp owns 4 tokens ----
    {
        const float4* fg4 = reinterpret_cast<const float4*>(feat + (size_t)blk * 64 * IN_);
        const float4* we4 = reinterpret_cast<const float4*>(g_wemb);
        float4 bias = *reinterpret_cast<const float4*>(b_emb + 4 * lane);
        float4 gm   = *reinterpret_cast<const float4*>(g_emb + 4 * lane);
        float4 bt   = *reinterpret_cast<const float4*>(beta_emb + 4 * lane);
        int t0 = wid * 4;
        float4 r[4];
        gemm16(we4, fg4, t0, lane, bias, r);
#pragma unroll
        for (int t = 0; t < 4; ++t) {
            float4 y = ln_warp(r[t], gm, bt);
            y = make_float4(fmaxf(y.x, 0.f), fmaxf(y.y, 0.f), fmaxf(y.z, 0.f), fmaxf(y.w, 0.f));
            hs4[(t0 + t) * 32 + lane] = y;
            store_ahl(ahl, t0 + t, lane, y);
        }
    }
    __syncthreads();

    // ---- Phase 2: enc GEMM (HMMA) -> qb, then LN/relu -> hs + ahl ----
    {
        float acc[4][4];
        gemm_mma(ahl, reinterpret_cast<const u64*>(g_bw), mt, ng, lane, acc);
        store_tile(qb, b_enc, mt, ng, lane, acc);
    }
    __syncthreads();
    {
        float4 gm = *reinterpret_cast<const float4*>(g_enc + 4 * lane);
        float4 bt = *reinterpret_cast<const float4*>(beta_enc + 4 * lane);
        int t0 = wid * 4;
#pragma unroll
        for (int t = 0; t < 4; ++t) {
            float4 x = qb4[(t0 + t) * P4 + lane];
            float4 y = ln_warp(x, gm, bt);
            y = make_float4(fmaxf(y.x, 0.f), fmaxf(y.y, 0.f), fmaxf(y.z, 0.f), fmaxf(y.w, 0.f));
            hs4[(t0 + t) * 32 + lane] = y;
            store_ahl(ahl, t0 + t, lane, y);
        }
    }
    __syncthreads();

    const float vk1 = sval[lane];
    const float vk2 = sval[lane + 32];
    const int hsel = lane >> 4;

    // ---- Phase 3: transformer layers ----
    for (int d = 0; d < 3; ++d) {
        {
            const u64* base = reinterpret_cast<const u64*>(g_bw);
            float acc[4][4];
            gemm_mma(ahl, base + (size_t)(1 + 3 * d) * 8192, mt, ng, lane, acc);
            store_tile(qb, bq + d * H_, mt, ng, lane, acc);
            gemm_mma(ahl, base + (size_t)(2 + 3 * d) * 8192, mt, ng, lane, acc);
            store_tile(kb, bk + d * H_, mt, ng, lane, acc);
            gemm_mma(ahl, base + (size_t)(3 + 3 * d) * 8192, mt, ng, lane, acc);
            store_tile(vb, bv + d * H_, mt, ng, lane, acc);
        }
        __syncthreads();

        // ---- attention (proven fp32 path); warp owns queries t0..t0+3 ----
        {
            const int t0 = wid * 4;
            float p1[2][4], p2[2][4];
#pragma unroll
            for (int head = 0; head < 2; ++head) {
                const int base = head * 16;
                u64 s1[4] = {}, s2[4] = {};
#pragma unroll 4
                for (int c = 0; c < 16; ++c) {
                    F4 k1; k1.v = kb4[lane * P4 + base + c];
                    F4 k2; k2.v = kb4[(lane + 32) * P4 + base + c];
#pragma unroll
                    for (int qq = 0; qq < 4; ++qq) {
                        F4 q; q.v = qb4[(t0 + qq) * P4 + base + c];
                        ffma2(s1[qq], q.u[0], k1.u[0]);
                        ffma2(s1[qq], q.u[1], k1.u[1]);
                        ffma2(s2[qq], q.u[0], k2.u[0]);
                        ffma2(s2[qq], q.u[1], k2.u[1]);
                    }
                }
#pragma unroll
                for (int qq = 0; qq < 4; ++qq) {
                    float vq = sval[t0 + qq];
                    float sc1 = hsum2(s1[qq]) * 0.125f + (1.f - vq * vk1) * -10000.f;
                    float sc2 = hsum2(s2[qq]) * 0.125f + (1.f - vq * vk2) * -10000.f;
                    float mx = warp_max(fmaxf(sc1, sc2));
                    float e1 = __expf(sc1 - mx), e2 = __expf(sc2 - mx);
                    float inv = 1.f / warp_sum(e1 + e2);
                    p1[head][qq] = e1 * inv;
                    p2[head][qq] = e2 * inv;
                }
            }
            u64 ca[4] = {}, cb[4] = {};
#pragma unroll 4
            for (int j = 0; j < 32; ++j) {
                F4 v; v.v = vb4[j * P4 + lane];
#pragma unroll
                for (int qq = 0; qq < 4; ++qq) {
                    float pj0 = __shfl_sync(0xffffffffu, p1[0][qq], j);
                    float pj1 = __shfl_sync(0xffffffffu, p1[1][qq], j);
                    float pj = hsel ? pj1 : pj0;
                    u64 pp = pk2(pj, pj);
                    ffma2(ca[qq], pp, v.u[0]);
                    ffma2(cb[qq], pp, v.u[1]);
                }
            }
#pragma unroll 4
            for (int j = 0; j < 32; ++j) {
                F4 v; v.v = vb4[(j + 32) * P4 + lane];
#pragma unroll
                for (int qq = 0; qq < 4; ++qq) {
                    float pj0 = __shfl_sync(0xffffffffu, p2[0][qq], j);
                    float pj1 = __shfl_sync(0xffffffffu, p2[1][qq], j);
                    float pj = hsel ? pj1 : pj0;
                    u64 pp = pk2(pj, pj);
                    ffma2(ca[qq], pp, v.u[0]);
                    ffma2(cb[qq], pp, v.u[1]);
                }
            }
            float4 gm = *reinterpret_cast<const float4*>(ln_g + d * H_ + 4 * lane);
            float4 bt = *reinterpret_cast<const float4*>(ln_b + d * H_ + 4 * lane);
#pragma unroll
            for (int qq = 0; qq < 4; ++qq) {
                int row = t0 + qq;
                float c0, c1, c2, c3;
                asm("mov.b64 {%0, %1}, %2;" : "=f"(c0), "=f"(c1) : "l"(ca[qq]));
                asm("mov.b64 {%0, %1}, %2;" : "=f"(c2), "=f"(c3) : "l"(cb[qq]));
                float4 hv = hs4[row * 32 + lane];
                float4 x = make_float4(fmaxf(c0, 0.f) + hv.x, fmaxf(c1, 0.f) + hv.y,
                                       fmaxf(c2, 0.f) + hv.z, fmaxf(c3, 0.f) + hv.w);
                float4 y = ln_warp(x, gm, bt);
                hs4[row * 32 + lane] = y;
                if (d < 2) store_ahl(ahl, row, lane, y);
            }
        }
        __syncthreads();
    }

    // ---- Phase 4: max over T (scratch = kb) ----
    {
        const int part = tid >> 7;          // 0..3
        const int hh   = tid & 127;
        float m = -3.4e38f;
#pragma unroll
        for (int t = 0; t < 16; ++t)
            m = fmaxf(m, hs[(part * 16 + t) * H_ + hh]);
        kb[part * H_ + hh] = m;
    }
    __syncthreads();
    if (tid < H_)
        out[(size_t)blk * H_ + tid] = fmaxf(fmaxf(kb[tid], kb[H_ + tid]),
                                            fmaxf(kb[2 * H_ + tid], kb[3 * H_ + tid]));
}

} // namespace

extern "C" void kernel_launch(void* const* d_in, const int* in_sizes, int n_in,
                              void* d_out, int out_size) {
    const float* feat     = (const float*)d_in[0];
    const float* masks    = (const float*)d_in[1];
    const float* W_emb    = (const float*)d_in[2];
    const float* b_emb    = (const float*)d_in[3];
    const float* g_emb    = (const float*)d_in[4];
    const float* beta_emb = (const float*)d_in[5];
    const float* W_enc    = (const float*)d_in[6];
    const float* b_enc    = (const float*)d_in[7];
    const float* g_enc    = (const float*)d_in[8];
    const float* beta_enc = (const float*)d_in[9];
    const float* Wq       = (const float*)d_in[10];
    const float* bq       = (const float*)d_in[11];
    const float* Wk       = (const float*)d_in[12];
    const float* bk       = (const float*)d_in[13];
    const float* Wv       = (const float*)d_in[14];
    const float* bv       = (const float*)d_in[15];
    const float* ln_g     = (const float*)d_in[16];
    const float* ln_b     = (const float*)d_in[17];
    float* out = (float*)d_out;

    int nseq = in_sizes[0] / (64 * IN_);   // 4096
    pack_emb<<<4, 256>>>(W_emb);
    pack_bw<<<(BW_U32 + 255) / 256, 256>>>(W_enc, Wq, Wk, Wv);

    // smem: 3*64*132 + 64*128 + 64 floats + 2*64*68 u32
    size_t smem = (size_t)(3 * 64 * 132 + 64 * 128 + 64) * 4 + (size_t)(2 * APL) * 4;
    cudaFuncSetAttribute(fused_lane_encoder,
                         cudaFuncAttributeMaxDynamicSharedMemorySize, (int)smem);
    fused_lane_encoder<<<nseq, NT, smem>>>(
        feat, masks, b_emb, g_emb, beta_emb, b_enc, g_enc, beta_enc,
        bq, bk, bv, ln_g, ln_b, out);
}

// round 14
// speedup vs baseline: 4.8602x; 1.5216x over previous
#include <cuda_runtime.h>
#include <cuda_bf16.h>

namespace {

typedef unsigned long long u64;
typedef unsigned int u32;

constexpr int IN_ = 16;
constexpr int H_ = 128;
constexpr int NT = 512;
constexpr float EPS = 1e-5f;
constexpr int ASTR = 68;          // bf16-plane row stride in u32 words (64 data + 4 pad; %32==4 -> conflict-free)
constexpr int APL = 64 * ASTR;    // hi->lo plane offset for 64-row planes (u32 words)
constexpr int PSTR = 36;          // P / V^T plane row stride in u32 words (32 data + 4 pad)
constexpr int PPL = 128 * PSTR;   // hi->lo plane offset for 128-row planes

// smem float offsets
constexpr int OFF_VB   = 0;        // 64x132 fp32 V
constexpr int OFF_HS   = 8448;     // 64x128 fp32 residual
constexpr int OFF_AHL  = 16640;    // activation bf16 hi/lo planes (2*APL u32)
constexpr int OFF_RA   = 25344;    // qpl (2*APL) -> vtpl (2*PPL)
constexpr int OFF_RB   = 34560;    // kpl (2*APL) -> ppl (2*PPL)
constexpr int OFF_RC   = 43776;    // enc scratch (64x132) / S (128x68) / ctx scratch (64x132)
constexpr int OFF_SVAL = 52480;    // 64
constexpr int SM_FLOATS = 52544;   // ~210KB

// B fragments packed for mma.m16n8k16: [mat 0..9][split 0..1][kt 0..7][nt 0..15][lane][2 u32]
constexpr int BW_U32 = 10 * 2 * 8 * 16 * 32 * 2;
__device__ __align__(16) u32 g_bw[BW_U32];
__device__ __align__(16) float2 g_wemb[8 * 128];

__device__ __forceinline__ u32 bfpair(float lo, float hi) {
    u32 r; asm("cvt.rn.bf16x2.f32 %0, %1, %2;" : "=r"(r) : "f"(hi), "f"(lo)); return r;
}
__device__ __forceinline__ float bfhi(float x) {
    return __bfloat162float(__float2bfloat16(x));
}

__global__ void pack_emb(const float* __restrict__ W) {
    int i = blockIdx.x * 256 + threadIdx.x;
    if (i >= 1024) return;
    int h = i & 127, m = i >> 7;
    g_wemb[i] = make_float2(W[(2 * m) * H_ + h], W[(2 * m + 1) * H_ + h]);
}

__global__ void pack_bw(const float* __restrict__ We, const float* __restrict__ Wq,
                        const float* __restrict__ Wk, const float* __restrict__ Wv) {
    int i = blockIdx.x * 256 + threadIdx.x;
    if (i >= BW_U32) return;
    int reg  = i & 1;
    int lane = (i >> 1) & 31;
    int nt   = (i >> 6) & 15;
    int kt   = (i >> 10) & 7;
    int s    = (i >> 13) & 1;
    int m    = i >> 14;
    const float* src;
    if (m == 0) src = We;
    else { int r = m - 1, d = r / 3, w = r % 3;
           src = (w == 0 ? Wq : (w == 1 ? Wk : Wv)) + d * H_ * H_; }
    int k0 = kt * 16 + (lane & 3) * 2 + reg * 8;
    int n  = nt * 8 + (lane >> 2);
    float x0 = src[k0 * H_ + n], x1 = src[(k0 + 1) * H_ + n];
    if (s) { x0 -= bfhi(x0); x1 -= bfhi(x1); }
    g_bw[i] = bfpair(x0, x1);
}

// ---------------- scalar helpers (proven) ----------------
union F4 { float4 v; u64 u[2]; };
__device__ __forceinline__ void ffma2(u64& d, u64 a, u64 b) {
    asm("fma.rn.f32x2 %0, %1, %2, %0;" : "+l"(d) : "l"(a), "l"(b));
}
__device__ __forceinline__ float hsum2(u64 v) {
    float lo, hi; asm("mov.b64 {%0, %1}, %2;" : "=f"(lo), "=f"(hi) : "l"(v));
    return lo + hi;
}
__device__ __forceinline__ float warp_sum(float v) {
#pragma unroll
    for (int o = 16; o > 0; o >>= 1) v += __shfl_xor_sync(0xffffffffu, v, o);
    return v;
}
__device__ __forceinline__ float4 ln_warp(float4 x, float4 gm, float4 bt) {
    float s  = warp_sum(x.x + x.y + x.z + x.w);
    float ss = warp_sum(x.x * x.x + x.y * x.y + x.z * x.z + x.w * x.w);
    float mean = s * (1.f / H_);
    float inv  = rsqrtf(ss * (1.f / H_) - mean * mean + EPS);
    return make_float4(gm.x * (x.x - mean) * inv + bt.x, gm.y * (x.y - mean) * inv + bt.y,
                       gm.z * (x.z - mean) * inv + bt.z, gm.w * (x.w - mean) * inv + bt.w);
}

// write bf16 hi/lo planes of one row-slice (cols 4l..4l+3)
__device__ __forceinline__ void store_ahl(u32* __restrict__ ahl, int row, int l, float4 y) {
    u32 h0 = bfpair(y.x, y.y), h1 = bfpair(y.z, y.w);
    u32 l0 = bfpair(y.x - bfhi(y.x), y.y - bfhi(y.y));
    u32 l1 = bfpair(y.z - bfhi(y.z), y.w - bfhi(y.w));
    *reinterpret_cast<u64*>(ahl + row * ASTR + 2 * l)       = (u64)h0 | ((u64)h1 << 32);
    *reinterpret_cast<u64*>(ahl + APL + row * ASTR + 2 * l) = (u64)l0 | ((u64)l1 << 32);
}

#define HMMA(d, a0, a1, a2, a3, b0, b1) \
    asm volatile("mma.sync.aligned.m16n8k16.row.col.f32.bf16.bf16.f32 " \
        "{%0,%1,%2,%3},{%4,%5,%6,%7},{%8,%9},{%0,%1,%2,%3};" \
        : "+f"((d)[0]), "+f"((d)[1]), "+f"((d)[2]), "+f"((d)[3]) \
        : "r"(a0), "r"(a1), "r"(a2), "r"(a3), "r"(b0), "r"(b1))

// one 64x128x128 GEMM tile-slice for this warp (proven)
__device__ __forceinline__ void gemm_mma(const u32* __restrict__ ahl,
                                         const u64* __restrict__ bw,
                                         int mt, int ng, int lane, float acc[4][4]) {
#pragma unroll
    for (int j = 0; j < 4; ++j)
#pragma unroll
        for (int r = 0; r < 4; ++r) acc[j][r] = 0.f;
    const int rb = (mt * 16 + (lane >> 2)) * ASTR;
#pragma unroll
    for (int kt = 0; kt < 8; ++kt) {
        const int ca = kt * 8 + (lane & 3);
        u32 ah0 = ahl[rb + ca],             ah1 = ahl[rb + 8 * ASTR + ca];
        u32 ah2 = ahl[rb + ca + 4],         ah3 = ahl[rb + 8 * ASTR + ca + 4];
        u32 al0 = ahl[APL + rb + ca],       al1 = ahl[APL + rb + 8 * ASTR + ca];
        u32 al2 = ahl[APL + rb + ca + 4],   al3 = ahl[APL + rb + 8 * ASTR + ca + 4];
#pragma unroll
        for (int j = 0; j < 4; ++j) {
            const int nt = ng * 4 + j;
            u64 bh = bw[(kt * 16 + nt) * 32 + lane];
            u64 bl = bw[4096 + (kt * 16 + nt) * 32 + lane];
            u32 bh0 = (u32)bh, bh1 = (u32)(bh >> 32);
            u32 bl0 = (u32)bl, bl1 = (u32)(bl >> 32);
            HMMA(acc[j], ah0, ah1, ah2, ah3, bh0, bh1);
            HMMA(acc[j], al0, al1, al2, al3, bh0, bh1);
            HMMA(acc[j], ah0, ah1, ah2, ah3, bl0, bl1);
        }
    }
}

// D tile (+bias) -> pitched fp32 buffer (132-float rows) (proven)
__device__ __forceinline__ void store_tile(float* __restrict__ buf,
                                           const float* __restrict__ biasg,
                                           int mt, int ng, int lane, float acc[4][4]) {
    const int g = lane >> 2, q = lane & 3;
#pragma unroll
    for (int j = 0; j < 4; ++j) {
        const int c = ng * 32 + j * 8 + q * 2;
        float2 bv = *reinterpret_cast<const float2*>(biasg + c);
        const int r = mt * 16 + g;
        *reinterpret_cast<float2*>(buf + r * 132 + c) =
            make_float2(acc[j][0] + bv.x, acc[j][1] + bv.y);
        *reinterpret_cast<float2*>(buf + (r + 8) * 132 + c) =
            make_float2(acc[j][2] + bv.x, acc[j][3] + bv.y);
    }
}

// D tile (+bias) -> bf16 hi/lo planes (row-major, stride ASTR) for Q/K
__device__ __forceinline__ void store_planes(u32* __restrict__ pl,
                                             const float* __restrict__ biasg,
                                             int mt, int ng, int lane, float acc[4][4]) {
    const int g = lane >> 2, t = lane & 3;
    const int r = mt * 16 + g;
#pragma unroll
    for (int j = 0; j < 4; ++j) {
        const int c = ng * 32 + j * 8 + t * 2;
        float2 bv = *reinterpret_cast<const float2*>(biasg + c);
        const int w = ng * 16 + j * 4 + t;
        float x0 = acc[j][0] + bv.x, x1 = acc[j][1] + bv.y;
        float x2 = acc[j][2] + bv.x, x3 = acc[j][3] + bv.y;
        pl[r * ASTR + w]             = bfpair(x0, x1);
        pl[(r + 8) * ASTR + w]       = bfpair(x2, x3);
        pl[APL + r * ASTR + w]       = bfpair(x0 - bfhi(x0), x1 - bfhi(x1));
        pl[APL + (r + 8) * ASTR + w] = bfpair(x2 - bfhi(x2), x3 - bfhi(x3));
    }
}

// scores S[head*64+q][k] = Q_head . K_head^T  (fp32-equivalent via 3-term split)
__device__ __forceinline__ void attn_scores(const u32* __restrict__ qpl,
                                            const u32* __restrict__ kpl,
                                            float* __restrict__ S,
                                            int wid, int lane) {
    const int head = wid >> 3, mt = (wid >> 1) & 3, nh = wid & 1;
    const int g = lane >> 2, t = lane & 3;
    float acc[4][4] = {};
    const int rb = (mt * 16 + g) * ASTR + head * 32;
#pragma unroll
    for (int kt = 0; kt < 4; ++kt) {
        const int ca = rb + kt * 8 + t;
        u32 ah0 = qpl[ca],           ah1 = qpl[8 * ASTR + ca];
        u32 ah2 = qpl[ca + 4],       ah3 = qpl[8 * ASTR + ca + 4];
        u32 al0 = qpl[APL + ca],     al1 = qpl[APL + 8 * ASTR + ca];
        u32 al2 = qpl[APL + ca + 4], al3 = qpl[APL + 8 * ASTR + ca + 4];
#pragma unroll
        for (int j = 0; j < 4; ++j) {
            const int kw = (nh * 32 + j * 8 + g) * ASTR + head * 32 + kt * 8 + t;
            u32 bh0 = kpl[kw],       bh1 = kpl[kw + 4];
            u32 bl0 = kpl[APL + kw], bl1 = kpl[APL + kw + 4];
            HMMA(acc[j], ah0, ah1, ah2, ah3, bh0, bh1);
            HMMA(acc[j], al0, al1, al2, al3, bh0, bh1);
            HMMA(acc[j], ah0, ah1, ah2, ah3, bl0, bl1);
        }
    }
    const int r = head * 64 + mt * 16 + g;
#pragma unroll
    for (int j = 0; j < 4; ++j) {
        const int c = nh * 32 + j * 8 + 2 * t;
        *reinterpret_cast<float2*>(S + r * 68 + c)       = make_float2(acc[j][0], acc[j][1]);
        *reinterpret_cast<float2*>(S + (r + 8) * 68 + c) = make_float2(acc[j][2], acc[j][3]);
    }
}

// softmax rows of S (scale + mask) -> P bf16 hi/lo planes (stride PSTR)
__device__ __forceinline__ void softmax_p(const float* __restrict__ S,
                                          u32* __restrict__ ppl,
                                          const float* __restrict__ sval, int tid) {
    const int row = tid >> 2, quad = tid & 3;
    const float vq = sval[row & 63];
    const float* srow = S + row * 68 + quad * 16;
    const float* svk  = sval + quad * 16;
    float s[16];
    float mx = -3.4e38f;
#pragma unroll
    for (int i = 0; i < 16; ++i) {
        s[i] = srow[i] * 0.125f + (1.f - vq * svk[i]) * -10000.f;
        mx = fmaxf(mx, s[i]);
    }
    mx = fmaxf(mx, __shfl_xor_sync(0xffffffffu, mx, 1));
    mx = fmaxf(mx, __shfl_xor_sync(0xffffffffu, mx, 2));
    float sum = 0.f;
#pragma unroll
    for (int i = 0; i < 16; ++i) { s[i] = __expf(s[i] - mx); sum += s[i]; }
    sum += __shfl_xor_sync(0xffffffffu, sum, 1);
    sum += __shfl_xor_sync(0xffffffffu, sum, 2);
    const float inv = 1.f / sum;
    u32* prow = ppl + row * PSTR + quad * 8;
#pragma unroll
    for (int ii = 0; ii < 8; ++ii) {
        float p0 = s[2 * ii] * inv, p1 = s[2 * ii + 1] * inv;
        prow[ii]       = bfpair(p0, p1);
        prow[PPL + ii] = bfpair(p0 - bfhi(p0), p1 - bfhi(p1));
    }
}

// vb fp32 (token-major) -> V^T bf16 hi/lo planes: row = h, word = key-pair
__device__ __forceinline__ void v_transpose(const float* __restrict__ vb,
                                            u32* __restrict__ vtpl, int tid) {
#pragma unroll
    for (int i = 0; i < 8; ++i) {
        const int idx = i * 512 + tid;
        const int h = idx & 127, w = idx >> 7;     // w = 0..31 key-pair
        float v0 = vb[(2 * w) * 132 + h];
        float v1 = vb[(2 * w + 1) * 132 + h];
        vtpl[h * PSTR + w]       = bfpair(v0, v1);
        vtpl[PPL + h * PSTR + w] = bfpair(v0 - bfhi(v0), v1 - bfhi(v1));
    }
}

// ctx = P @ V  -> fp32 scratch (pitch 132)
__device__ __forceinline__ void attn_ctx(const u32* __restrict__ ppl,
                                         const u32* __restrict__ vtpl,
                                         float* __restrict__ ctx,
                                         int wid, int lane) {
    const int mt = wid & 3, ng = wid >> 2;
    const int head = ng >> 1;
    const int g = lane >> 2, t = lane & 3;
    float acc[4][4] = {};
    const int rb = (head * 64 + mt * 16 + g) * PSTR;
#pragma unroll
    for (int kt = 0; kt < 4; ++kt) {
        const int ca = rb + kt * 8 + t;
        u32 ah0 = ppl[ca],           ah1 = ppl[8 * PSTR + ca];
        u32 ah2 = ppl[ca + 4],       ah3 = ppl[8 * PSTR + ca + 4];
        u32 al0 = ppl[PPL + ca],     al1 = ppl[PPL + 8 * PSTR + ca];
        u32 al2 = ppl[PPL + ca + 4], al3 = ppl[PPL + 8 * PSTR + ca + 4];
#pragma unroll
        for (int j = 0; j < 4; ++j) {
            const int vw = (ng * 32 + j * 8 + g) * PSTR + kt * 8 + t;
            u32 bh0 = vtpl[vw],       bh1 = vtpl[vw + 4];
            u32 bl0 = vtpl[PPL + vw], bl1 = vtpl[PPL + vw + 4];
            HMMA(acc[j], ah0, ah1, ah2, ah3, bh0, bh1);
            HMMA(acc[j], al0, al1, al2, al3, bh0, bh1);
            HMMA(acc[j], ah0, ah1, ah2, ah3, bl0, bl1);
        }
    }
    const int r = mt * 16 + g;
#pragma unroll
    for (int j = 0; j < 4; ++j) {
        const int c = ng * 32 + j * 8 + 2 * t;
        *reinterpret_cast<float2*>(ctx + r * 132 + c)       = make_float2(acc[j][0], acc[j][1]);
        *reinterpret_cast<float2*>(ctx + (r + 8) * 132 + c) = make_float2(acc[j][2], acc[j][3]);
    }
}

// K=16 emb gemm, 4 tokens, x from global (proven)
__device__ __forceinline__ void gemm16(const float4* __restrict__ wp4,
                                       const float4* __restrict__ xg4,
                                       int t0, int l, float4 bias, float4 res[4]) {
    u64 acc[4][4] = {};
#pragma unroll
    for (int kb = 0; kb < 4; ++kb) {
        const float4* w0 = wp4 + (2 * kb) * 64 + 2 * l;
        const float4* w1 = wp4 + (2 * kb + 1) * 64 + 2 * l;
        F4 A0, A1, B0, B1;
        A0.v = w0[0]; A1.v = w0[1]; B0.v = w1[0]; B1.v = w1[1];
#pragma unroll
        for (int t = 0; t < 4; ++t) {
            F4 x; x.v = xg4[(t0 + t) * 4 + kb];
            ffma2(acc[t][0], x.u[0], A0.u[0]); ffma2(acc[t][0], x.u[1], B0.u[0]);
            ffma2(acc[t][1], x.u[0], A0.u[1]); ffma2(acc[t][1], x.u[1], B0.u[1]);
            ffma2(acc[t][2], x.u[0], A1.u[0]); ffma2(acc[t][2], x.u[1], B1.u[0]);
            ffma2(acc[t][3], x.u[0], A1.u[1]); ffma2(acc[t][3], x.u[1], B1.u[1]);
        }
    }
#pragma unroll
    for (int t = 0; t < 4; ++t)
        res[t] = make_float4(hsum2(acc[t][0]) + bias.x, hsum2(acc[t][1]) + bias.y,
                             hsum2(acc[t][2]) + bias.z, hsum2(acc[t][3]) + bias.w);
}

// ================= main fused kernel: 1 sequence per CTA =================
__global__ void __launch_bounds__(NT, 1) fused_lane_encoder(
    const float* __restrict__ feat, const float* __restrict__ masks,
    const float* __restrict__ b_emb, const float* __restrict__ g_emb,
    const float* __restrict__ beta_emb,
    const float* __restrict__ b_enc, const float* __restrict__ g_enc,
    const float* __restrict__ beta_enc,
    const float* __restrict__ bq, const float* __restrict__ bk,
    const float* __restrict__ bv,
    const float* __restrict__ ln_g, const float* __restrict__ ln_b,
    float* __restrict__ out)
{
    extern __shared__ float smem[];
    float* const vb   = smem + OFF_VB;
    float* const hs   = smem + OFF_HS;
    u32*   const ahl  = reinterpret_cast<u32*>(smem + OFF_AHL);
    u32*   const RA   = reinterpret_cast<u32*>(smem + OFF_RA);
    u32*   const RB   = reinterpret_cast<u32*>(smem + OFF_RB);
    float* const RC   = smem + OFF_RC;
    float* const sval = smem + OFF_SVAL;

    float4* const hs4 = reinterpret_cast<float4*>(hs);

    const int tid  = threadIdx.x;
    const int lane = tid & 31;
    const int wid  = tid >> 5;       // 0..15
    const int mt   = wid & 3;
    const int ng   = wid >> 2;
    const int blk  = blockIdx.x;

    if (tid < 64) sval[tid] = 1.0f - masks[(size_t)blk * 64 + tid];

    // ---- Phase 1: emb = relu(LN(feat @ W_emb + b)); warp owns 4 tokens ----
    {
        const float4* fg4 = reinterpret_cast<const float4*>(feat + (size_t)blk * 64 * IN_);
        const float4* we4 = reinterpret_cast<const float4*>(g_wemb);
        float4 bias = *reinterpret_cast<const float4*>(b_emb + 4 * lane);
        float4 gm   = *reinterpret_cast<const float4*>(g_emb + 4 * lane);
        float4 bt   = *reinterpret_cast<const float4*>(beta_emb + 4 * lane);
        int t0 = wid * 4;
        float4 r[4];
        gemm16(we4, fg4, t0, lane, bias, r);
#pragma unroll
        for (int t = 0; t < 4; ++t) {
            float4 y = ln_warp(r[t], gm, bt);
            y = make_float4(fmaxf(y.x, 0.f), fmaxf(y.y, 0.f), fmaxf(y.z, 0.f), fmaxf(y.w, 0.f));
            hs4[(t0 + t) * 32 + lane] = y;
            store_ahl(ahl, t0 + t, lane, y);
        }
    }
    __syncthreads();

    // ---- Phase 2: enc GEMM (HMMA) -> RC, then LN/relu -> hs + ahl ----
    {
        float acc[4][4];
        gemm_mma(ahl, reinterpret_cast<const u64*>(g_bw), mt, ng, lane, acc);
        store_tile(RC, b_enc, mt, ng, lane, acc);
    }
    __syncthreads();
    {
        const float4* rc4 = reinterpret_cast<const float4*>(RC);
        float4 gm = *reinterpret_cast<const float4*>(g_enc + 4 * lane);
        float4 bt = *reinterpret_cast<const float4*>(beta_enc + 4 * lane);
        int t0 = wid * 4;
#pragma unroll
        for (int t = 0; t < 4; ++t) {
            float4 x = rc4[(t0 + t) * 33 + lane];
            float4 y = ln_warp(x, gm, bt);
            y = make_float4(fmaxf(y.x, 0.f), fmaxf(y.y, 0.f), fmaxf(y.z, 0.f), fmaxf(y.w, 0.f));
            hs4[(t0 + t) * 32 + lane] = y;
            store_ahl(ahl, t0 + t, lane, y);
        }
    }
    __syncthreads();

    // ---- Phase 3: transformer layers (fully HMMA) ----
    for (int d = 0; d < 3; ++d) {
        {
            const u64* base = reinterpret_cast<const u64*>(g_bw);
            float acc[4][4];
            gemm_mma(ahl, base + (size_t)(1 + 3 * d) * 8192, mt, ng, lane, acc);
            store_planes(RA, bq + d * H_, mt, ng, lane, acc);       // Q planes
            gemm_mma(ahl, base + (size_t)(2 + 3 * d) * 8192, mt, ng, lane, acc);
            store_planes(RB, bk + d * H_, mt, ng, lane, acc);       // K planes
            gemm_mma(ahl, base + (size_t)(3 + 3 * d) * 8192, mt, ng, lane, acc);
            store_tile(vb, bv + d * H_, mt, ng, lane, acc);         // V fp32
        }
        __syncthreads();

        attn_scores(RA, RB, RC, wid, lane);                         // S = Q.K^T
        __syncthreads();

        softmax_p(RC, RB, sval, tid);                               // P planes (over kpl)
        v_transpose(vb, RA, tid);                                   // V^T planes (over qpl)
        __syncthreads();

        attn_ctx(RB, RA, RC, wid, lane);                            // ctx (over S)
        __syncthreads();

        {   // residual + LN epilogue (warp-local)
            const float4* rc4 = reinterpret_cast<const float4*>(RC);
            float4 gm = *reinterpret_cast<const float4*>(ln_g + d * H_ + 4 * lane);
            float4 bt = *reinterpret_cast<const float4*>(ln_b + d * H_ + 4 * lane);
            int t0 = wid * 4;
#pragma unroll
            for (int t = 0; t < 4; ++t) {
                int row = t0 + t;
                float4 cv = rc4[row * 33 + lane];
                float4 hv = hs4[row * 32 + lane];
                float4 x = make_float4(fmaxf(cv.x, 0.f) + hv.x, fmaxf(cv.y, 0.f) + hv.y,
                                       fmaxf(cv.z, 0.f) + hv.z, fmaxf(cv.w, 0.f) + hv.w);
                float4 y = ln_warp(x, gm, bt);
                hs4[row * 32 + lane] = y;
                if (d < 2) store_ahl(ahl, row, lane, y);
            }
        }
        __syncthreads();
    }

    // ---- Phase 4: max over T (scratch = RC) ----
    {
        const int part = tid >> 7;
        const int hh   = tid & 127;
        float m = -3.4e38f;
#pragma unroll
        for (int t = 0; t < 16; ++t)
            m = fmaxf(m, hs[(part * 16 + t) * H_ + hh]);
        RC[part * H_ + hh] = m;
    }
    __syncthreads();
    if (tid < H_)
        out[(size_t)blk * H_ + tid] = fmaxf(fmaxf(RC[tid], RC[H_ + tid]),
                                            fmaxf(RC[2 * H_ + tid], RC[3 * H_ + tid]));
}

} // namespace

extern "C" void kernel_launch(void* const* d_in, const int* in_sizes, int n_in,
                              void* d_out, int out_size) {
    const float* feat     = (const float*)d_in[0];
    const float* masks    = (const float*)d_in[1];
    const float* W_emb    = (const float*)d_in[2];
    const float* b_emb    = (const float*)d_in[3];
    const float* g_emb    = (const float*)d_in[4];
    const float* beta_emb = (const float*)d_in[5];
    const float* W_enc    = (const float*)d_in[6];
    const float* b_enc    = (const float*)d_in[7];
    const float* g_enc    = (const float*)d_in[8];
    const float* beta_enc = (const float*)d_in[9];
    const float* Wq       = (const float*)d_in[10];
    const float* bq       = (const float*)d_in[11];
    const float* Wk       = (const float*)d_in[12];
    const float* bk       = (const float*)d_in[13];
    const float* Wv       = (const float*)d_in[14];
    const float* bv       = (const float*)d_in[15];
    const float* ln_g     = (const float*)d_in[16];
    const float* ln_b     = (const float*)d_in[17];
    float* out = (float*)d_out;

    int nseq = in_sizes[0] / (64 * IN_);   // 4096
    pack_emb<<<4, 256>>>(W_emb);
    pack_bw<<<(BW_U32 + 255) / 256, 256>>>(W_enc, Wq, Wk, Wv);

    size_t smem = (size_t)SM_FLOATS * 4;   // ~210KB
    cudaFuncSetAttribute(fused_lane_encoder,
                         cudaFuncAttributeMaxDynamicSharedMemorySize, (int)smem);
    fused_lane_encoder<<<nseq, NT, smem>>>(
        feat, masks, b_emb, g_emb, beta_emb, b_enc, g_enc, beta_enc,
        bq, bk, bv, ln_g, ln_b, out);
}